// round 11
// baseline (speedup 1.0000x reference)
#include <cuda_runtime.h>
#include <cuda_fp16.h>
#include <cstdint>
#include <cstddef>

// ---------------------------------------------------------------- constants
#define D_DIM   256
#define K_CODES 1024
#define P_PER_B 1024
#define N_BATCH 64
#define N_PTS   (N_BATCH * P_PER_B)    // 65536
#define MP      256                    // points per CTA
#define NTILE   64                     // codes per tile
#define TILES   (K_CODES / NTILE)      // 16
#define NTHR    512                    // 16 warps
#define TAU     8e-4f
#define CAP     3100

#define PITCH_B 528                    // 256 fp16 + 8 pad (row = 33 x 16B -> conflict-free)
#define A_ROW   528

#define OFF_A      0
#define OFF_B0     135168
#define OFF_B1     168960
#define OFF_ROWMIN 202752
#define OFF_SLOT   203776
#define OFF_ZZS    205824
#define OFF_CNT    206848
#define OFF_LIST   206864
#define SMEM_TOTAL (206864 + CAP * 8)  // 231664

// ---------------------------------------------------------------- scratch
__device__ float g_e2[K_CODES];
__device__ float g_zzp[8][N_PTS];                                  // zz partials per 32-d block
__device__ __align__(16) uint16_t g_zh[(size_t)N_PTS * D_DIM];     // z fp16 [p][d]
__device__ __align__(16) uint16_t g_eb[(size_t)K_CODES * D_DIM];   // emb fp16 [k][d]

// ---------------------------------------------------------------- helpers
__device__ __forceinline__ uint32_t smem_u32(const void* p) {
    uint32_t a;
    asm("{ .reg .u64 t; cvta.to.shared.u64 t, %1; cvt.u32.u64 %0, t; }" : "=r"(a) : "l"(p));
    return a;
}
__device__ __forceinline__ void ldmatrix_x4(uint32_t& r0, uint32_t& r1,
                                            uint32_t& r2, uint32_t& r3, uint32_t a) {
    asm volatile("ldmatrix.sync.aligned.m8n8.x4.shared.b16 {%0,%1,%2,%3}, [%4];"
                 : "=r"(r0), "=r"(r1), "=r"(r2), "=r"(r3) : "r"(a));
}
// fp16 x fp16 -> fp16 accumulate (2x rate vs f32-accum on the legacy pipe)
__device__ __forceinline__ void mma_f16acc(uint32_t* c, const uint32_t* a,
                                           uint32_t b0, uint32_t b1) {
    asm volatile(
        "mma.sync.aligned.m16n8k16.row.col.f16.f16.f16.f16 "
        "{%0,%1}, {%2,%3,%4,%5}, {%6,%7}, {%0,%1};"
        : "+r"(c[0]), "+r"(c[1])
        : "r"(a[0]), "r"(a[1]), "r"(a[2]), "r"(a[3]), "r"(b0), "r"(b1));
}
__device__ __forceinline__ void cp16(uint32_t dst, const void* src) {
    asm volatile("cp.async.cg.shared.global [%0], [%1], 16;" :: "r"(dst), "l"(src) : "memory");
}
// order-preserving float<->uint
__device__ __forceinline__ uint32_t fenc(float f) {
    uint32_t b = __float_as_uint(f);
    return b ^ ((b & 0x80000000u) ? 0xFFFFFFFFu : 0x80000000u);
}
__device__ __forceinline__ float fdec(uint32_t u) {
    uint32_t b = u ^ ((u & 0x80000000u) ? 0x80000000u : 0xFFFFFFFFu);
    return __uint_as_float(b);
}

// ---------------------------------------------------------------- prep (merged)
// blockIdx.z < 64 : z transpose NCHW -> g_zh fp16 [p][d] + zz partials
// blockIdx.z == 64: emb -> g_eb fp16 + g_e2 (4 codes per block)
__global__ void prep_kernel(const float* __restrict__ z, const float* __restrict__ emb) {
    if (blockIdx.z == N_BATCH) {
        __shared__ float part[8];
        int kb = (blockIdx.y * 32 + blockIdx.x) * 4;
        int d = threadIdx.x + threadIdx.y * 32;      // 0..255
        #pragma unroll
        for (int i = 0; i < 4; ++i) {
            int k = kb + i;
            float v = emb[(size_t)k * D_DIM + d];
            g_eb[(size_t)k * D_DIM + d] = __half_as_ushort(__float2half_rn(v));
            float s = v * v;
            #pragma unroll
            for (int o = 16; o > 0; o >>= 1) s += __shfl_xor_sync(0xffffffffu, s, o);
            if ((d & 31) == 0) part[d >> 5] = s;
            __syncthreads();
            if (d == 0) {
                float t = 0.f;
                #pragma unroll
                for (int j = 0; j < 8; ++j) t += part[j];
                g_e2[k] = t;
            }
            __syncthreads();
        }
        return;
    }
    __shared__ float tile[32][33];
    int b = blockIdx.z, d0 = blockIdx.y * 32, p0 = blockIdx.x * 32;
    int tx = threadIdx.x, ty = threadIdx.y;          // (32,8)
    #pragma unroll
    for (int r = 0; r < 4; ++r)
        tile[ty + 8 * r][tx] = z[((size_t)b * D_DIM + d0 + ty + 8 * r) * P_PER_B + p0 + tx];
    __syncthreads();
    #pragma unroll
    for (int r = 0; r < 4; ++r) {
        int pl = ty + 8 * r;
        float v = tile[tx][pl];
        g_zh[((size_t)b * P_PER_B + p0 + pl) * D_DIM + d0 + tx] =
            __half_as_ushort(__float2half_rn(v));
        float s = v * v;
        #pragma unroll
        for (int o2 = 16; o2 > 0; o2 >>= 1) s += __shfl_xor_sync(0xffffffffu, s, o2);
        if (tx == 0) g_zzp[d0 >> 5][b * P_PER_B + p0 + pl] = s;
    }
}

// ---------------------------------------------------------------- main
// grid 256, block 512 (16 warps): warp (w&3)=64-row M slab, (w>>2)=16-col N quarter.
__global__ void __launch_bounds__(NTHR, 1)
vq_hmma_kernel(const float* __restrict__ z, const float* __restrict__ emb,
               float* __restrict__ out) {
    extern __shared__ __align__(16) char sm[];
    const uint32_t sb = smem_u32(sm);
    const int tid = threadIdx.x, w = tid >> 5, l = tid & 31;
    const int warp_m = w & 3, warp_n = w >> 2;       // 4 x 4
    const int m_base = blockIdx.x * MP;
    const int b_idx = m_base >> 10, pp = m_base & 1023;

    uint32_t* rowmin_u = reinterpret_cast<uint32_t*>(sm + OFF_ROWMIN);
    unsigned long long* slot = reinterpret_cast<unsigned long long*>(sm + OFF_SLOT);
    float* zzs  = reinterpret_cast<float*>(sm + OFF_ZZS);
    uint2* list = reinterpret_cast<uint2*>(sm + OFF_LIST);
    int*   cnt  = reinterpret_cast<int*>(sm + OFF_CNT);

    if (tid < MP) {
        rowmin_u[tid] = 0xFFFFFFFFu;
        slot[tid] = ~0ull;
        float p0 = g_zzp[0][m_base + tid], p1 = g_zzp[1][m_base + tid];
        float p2 = g_zzp[2][m_base + tid], p3 = g_zzp[3][m_base + tid];
        float p4 = g_zzp[4][m_base + tid], p5 = g_zzp[5][m_base + tid];
        float p6 = g_zzp[6][m_base + tid], p7 = g_zzp[7][m_base + tid];
        zzs[tid] = ((p0 + p1) + (p2 + p3)) + ((p4 + p5) + (p6 + p7));
    }
    if (tid == 0) *cnt = 0;

    // ---- A (256 rows fp16) + B tile 0 via cp.async
    {
        const char* asrc = reinterpret_cast<const char*>(g_zh + (size_t)m_base * D_DIM);
        for (int q = tid; q < MP * 32; q += NTHR) {
            int row = q >> 5, ch = q & 31;
            cp16(sb + OFF_A + row * A_ROW + ch * 16, asrc + row * 512 + ch * 16);
        }
        const char* bsrc = reinterpret_cast<const char*>(g_eb);
        for (int q = tid; q < NTILE * 32; q += NTHR) {
            int row = q >> 5, ch = q & 31;
            cp16(sb + OFF_B0 + row * PITCH_B + ch * 16, bsrc + row * 512 + ch * 16);
        }
        asm volatile("cp.async.commit_group;" ::: "memory");
    }

    float rm[4][2];                       // running per-row min (registers)
    #pragma unroll
    for (int mt = 0; mt < 4; ++mt) { rm[mt][0] = 3.4e38f; rm[mt][1] = 3.4e38f; }

    for (int t = 0; t < TILES; ++t) {
        if (t + 1 < TILES) {
            const char* src = reinterpret_cast<const char*>(g_eb) + (size_t)(t + 1) * NTILE * 512;
            uint32_t dstb = sb + (((t + 1) & 1) ? OFF_B1 : OFF_B0);
            for (int q = tid; q < NTILE * 32; q += NTHR) {
                int row = q >> 5, ch = q & 31;
                cp16(dstb + row * PITCH_B + ch * 16, src + row * 512 + ch * 16);
            }
            asm volatile("cp.async.commit_group;" ::: "memory");
            asm volatile("cp.async.wait_group 1;" ::: "memory");
        } else {
            asm volatile("cp.async.wait_group 0;" ::: "memory");
        }
        __syncthreads();

        const uint32_t Bb = sb + ((t & 1) ? OFF_B1 : OFF_B0);

        uint32_t acc[4][2][2];            // fp16x2 accumulators
        #pragma unroll
        for (int mt = 0; mt < 4; ++mt)
            #pragma unroll
            for (int nt = 0; nt < 2; ++nt) { acc[mt][nt][0] = 0u; acc[mt][nt][1] = 0u; }

        #pragma unroll
        for (int ks = 0; ks < 16; ++ks) {
            uint32_t a[4][4];
            #pragma unroll
            for (int mt = 0; mt < 4; ++mt) {
                uint32_t addr = sb + OFF_A
                              + (warp_m * 64 + mt * 16 + (l & 15)) * A_ROW
                              + (ks * 16 + ((l >> 4) & 1) * 8) * 2;
                ldmatrix_x4(a[mt][0], a[mt][1], a[mt][2], a[mt][3], addr);
            }
            uint32_t b[4];
            {
                uint32_t addr = Bb
                              + (warp_n * 16 + ((l >> 4) & 1) * 8 + (l & 7)) * PITCH_B
                              + (ks * 16 + ((l >> 3) & 1) * 8) * 2;
                ldmatrix_x4(b[0], b[1], b[2], b[3], addr);
            }
            #pragma unroll
            for (int mt = 0; mt < 4; ++mt)
                #pragma unroll
                for (int nt = 0; nt < 2; ++nt)
                    mma_f16acc(acc[mt][nt], a[mt], b[nt * 2], b[nt * 2 + 1]);
        }

        // ---- epilogue: unpack fp16 dots -> fp32 scores -> row-min -> gate
        const int n0 = t * NTILE + warp_n * 16;
        float e2v[2][2];
        #pragma unroll
        for (int nt = 0; nt < 2; ++nt) {
            e2v[nt][0] = __ldg(&g_e2[n0 + nt * 8 + (l & 3) * 2]);
            e2v[nt][1] = __ldg(&g_e2[n0 + nt * 8 + (l & 3) * 2 + 1]);
        }
        float sc[4][2][4];
        float rmin[4][2];
        #pragma unroll
        for (int mt = 0; mt < 4; ++mt) { rmin[mt][0] = 3.4e38f; rmin[mt][1] = 3.4e38f; }
        #pragma unroll
        for (int mt = 0; mt < 4; ++mt)
            #pragma unroll
            for (int nt = 0; nt < 2; ++nt) {
                float2 f01 = __half22float2(*reinterpret_cast<__half2*>(&acc[mt][nt][0]));
                float2 f23 = __half22float2(*reinterpret_cast<__half2*>(&acc[mt][nt][1]));
                float s0 = __fmaf_rn(-2.f, f01.x, e2v[nt][0]);
                float s1 = __fmaf_rn(-2.f, f01.y, e2v[nt][1]);
                float s2 = __fmaf_rn(-2.f, f23.x, e2v[nt][0]);
                float s3 = __fmaf_rn(-2.f, f23.y, e2v[nt][1]);
                sc[mt][nt][0] = s0; sc[mt][nt][1] = s1;
                sc[mt][nt][2] = s2; sc[mt][nt][3] = s3;
                rmin[mt][0] = fminf(rmin[mt][0], fminf(s0, s1));
                rmin[mt][1] = fminf(rmin[mt][1], fminf(s2, s3));
            }
        #pragma unroll
        for (int mt = 0; mt < 4; ++mt)
            #pragma unroll
            for (int h = 0; h < 2; ++h) {
                float v = rmin[mt][h];                        // quad shares rows
                v = fminf(v, __shfl_xor_sync(0xffffffffu, v, 1));
                v = fminf(v, __shfl_xor_sync(0xffffffffu, v, 2));
                rmin[mt][h] = v;
            }
        if ((l & 3) == 0) {
            #pragma unroll
            for (int mt = 0; mt < 4; ++mt)
                #pragma unroll
                for (int h = 0; h < 2; ++h)
                    atomicMin(&rowmin_u[warp_m * 64 + mt * 16 + (l >> 2) + h * 8],
                              fenc(rmin[mt][h]));
        }
        #pragma unroll
        for (int mt = 0; mt < 4; ++mt)
            #pragma unroll
            for (int h = 0; h < 2; ++h) {
                // own fresh min + possibly-stale shared (stale only admits extras)
                float sh = fdec(rowmin_u[warp_m * 64 + mt * 16 + (l >> 2) + h * 8]);
                rm[mt][h] = fminf(fminf(rm[mt][h], rmin[mt][h]), sh);
            }
        #pragma unroll
        for (int mt = 0; mt < 4; ++mt)
            #pragma unroll
            for (int nt = 0; nt < 2; ++nt)
                #pragma unroll
                for (int c = 0; c < 4; ++c) {
                    float s = sc[mt][nt][c];
                    if (s <= rm[mt][c >> 1] + TAU) {
                        int row  = warp_m * 64 + mt * 16 + (l >> 2) + (c >> 1) * 8;
                        int code = n0 + nt * 8 + (l & 3) * 2 + (c & 1);
                        int pos = atomicAdd(cnt, 1);
                        if (pos < CAP)
                            list[pos] = make_uint2((uint32_t)(row << 10) | code,
                                                   __float_as_uint(s));
                    }
                }
        __syncthreads();   // readers done before buffer reuse; rowmin published
    }

    const float* zc = z + (size_t)b_idx * D_DIM * P_PER_B + pp;   // + row + d*1024

    int total = *cnt;
    if (total <= CAP) {
        // ---- exact fp32 refine (z read from original NCHW layout; L2-resident slab)
        for (int i = tid; i < total; i += NTHR) {
            uint2 ent = list[i];
            int row = ent.x >> 10, code = ent.x & 1023;
            if (__uint_as_float(ent.y) > fdec(rowmin_u[row]) + TAU) continue;
            const float* zr = zc + row;
            const float* er = emb + (size_t)code * D_DIM;
            float a0 = 0.f, a1 = 0.f, a2 = 0.f, a3 = 0.f;
            #pragma unroll 8
            for (int d = 0; d < D_DIM; d += 4) {
                float4 e4 = *reinterpret_cast<const float4*>(er + d);
                a0 = __fmaf_rn(__ldg(zr + (size_t)(d + 0) * P_PER_B), e4.x, a0);
                a1 = __fmaf_rn(__ldg(zr + (size_t)(d + 1) * P_PER_B), e4.y, a1);
                a2 = __fmaf_rn(__ldg(zr + (size_t)(d + 2) * P_PER_B), e4.z, a2);
                a3 = __fmaf_rn(__ldg(zr + (size_t)(d + 3) * P_PER_B), e4.w, a3);
            }
            float dot = (a0 + a1) + (a2 + a3);
            float q = __fadd_rn(__fmaf_rn(-2.f, dot, zzs[row]), g_e2[code]);
            unsigned long long key =
                ((unsigned long long)__float_as_uint(q) << 32) | (uint32_t)code;
            atomicMin(&slot[row], key);
        }
    } else if (tid < MP) {
        // overflow fallback (prob ~0): brute-force own point exactly
        const float* zr = zc + tid;
        float zzv = zzs[tid];
        unsigned long long best = ~0ull;
        for (int code = 0; code < K_CODES; ++code) {
            const float* er = emb + (size_t)code * D_DIM;
            float a0 = 0.f, a1 = 0.f, a2 = 0.f, a3 = 0.f;
            #pragma unroll 4
            for (int d = 0; d < D_DIM; d += 4) {
                float4 e4 = *reinterpret_cast<const float4*>(er + d);
                a0 = __fmaf_rn(__ldg(zr + (size_t)(d + 0) * P_PER_B), e4.x, a0);
                a1 = __fmaf_rn(__ldg(zr + (size_t)(d + 1) * P_PER_B), e4.y, a1);
                a2 = __fmaf_rn(__ldg(zr + (size_t)(d + 2) * P_PER_B), e4.z, a2);
                a3 = __fmaf_rn(__ldg(zr + (size_t)(d + 3) * P_PER_B), e4.w, a3);
            }
            float dot = (a0 + a1) + (a2 + a3);
            float q = __fadd_rn(__fmaf_rn(-2.f, dot, zzv), g_e2[code]);
            unsigned long long key =
                ((unsigned long long)__float_as_uint(q) << 32) | (uint32_t)code;
            if (key < best) best = key;
        }
        slot[tid] = best;
    }
    __syncthreads();

    if (tid < MP)
        out[m_base + tid] = (float)(uint32_t)(slot[tid] & 0xffffffffull);
}

// ---------------------------------------------------------------- launch
extern "C" void kernel_launch(void* const* d_in, const int* in_sizes, int n_in,
                              void* d_out, int out_size) {
    const float* z   = (const float*)d_in[0];
    const float* emb = (const float*)d_in[1];
    if (n_in >= 2 && in_sizes[0] == K_CODES * D_DIM) {
        emb = (const float*)d_in[0];
        z   = (const float*)d_in[1];
    }
    float* out = (float*)d_out;

    static int smem_set = 0;
    if (!smem_set) {
        cudaFuncSetAttribute(vq_hmma_kernel,
                             cudaFuncAttributeMaxDynamicSharedMemorySize, SMEM_TOTAL);
        smem_set = 1;
    }

    prep_kernel<<<dim3(32, 8, N_BATCH + 1), dim3(32, 8)>>>(z, emb);
    vq_hmma_kernel<<<N_PTS / MP, NTHR, SMEM_TOTAL>>>(z, emb, out);
}

// round 12
// speedup vs baseline: 1.6419x; 1.6419x over previous
#include <cuda_runtime.h>
#include <cuda_bf16.h>
#include <cstdint>
#include <cstddef>

// ---------------------------------------------------------------- constants
#define D_DIM   256
#define K_CODES 1024
#define P_PER_B 1024
#define N_BATCH 64
#define N_PTS   (N_BATCH * P_PER_B)    // 65536
#define MP      256                    // points per CTA
#define NTILE   64                     // codes per tile
#define TILES   (K_CODES / NTILE)      // 16
#define NTHR    256                    // 8 warps
#define TAU     4e-4f
#define CAP     3100

#define PITCH_H 264                    // padded row pitch in halves (528 B)
#define PITCH_B 528                    // bytes
#define A_ROW   528
#define A_BYTES  (MP * PITCH_B)        // 135168
#define BT_BYTES (NTILE * PITCH_B)     // 33792

#define OFF_A      0
#define OFF_B0     135168
#define OFF_B1     168960
#define OFF_ROWMIN 202752
#define OFF_SLOT   203776
#define OFF_ZZS    205824
#define OFF_CNT    206848
#define OFF_MBAR   206856              // 3 x 8B: A, buf0, buf1
#define OFF_LIST   206880
#define SMEM_TOTAL (206880 + CAP * 8)  // 231680

// ---------------------------------------------------------------- scratch
__device__ float g_e2[K_CODES];
__device__ float g_zzp[8][N_PTS];                                    // zz partials / 32-d block
__device__ __align__(16) float    g_zt[(size_t)N_PTS * D_DIM];       // z fp32 [p][d]
__device__ __align__(16) uint16_t g_zh[(size_t)N_PTS * PITCH_H];     // z bf16, 528B pitch
__device__ __align__(16) uint16_t g_eb[(size_t)K_CODES * PITCH_H];   // emb bf16, 528B pitch

// ---------------------------------------------------------------- helpers
__device__ __forceinline__ uint32_t smem_u32(const void* p) {
    uint32_t a;
    asm("{ .reg .u64 t; cvta.to.shared.u64 t, %1; cvt.u32.u64 %0, t; }" : "=r"(a) : "l"(p));
    return a;
}
__device__ __forceinline__ void ldmatrix_x4(uint32_t& r0, uint32_t& r1,
                                            uint32_t& r2, uint32_t& r3, uint32_t a) {
    asm volatile("ldmatrix.sync.aligned.m8n8.x4.shared.b16 {%0,%1,%2,%3}, [%4];"
                 : "=r"(r0), "=r"(r1), "=r"(r2), "=r"(r3) : "r"(a));
}
__device__ __forceinline__ void mma_bf16(float* c, const uint32_t* a,
                                         uint32_t b0, uint32_t b1) {
    asm volatile(
        "mma.sync.aligned.m16n8k16.row.col.f32.bf16.bf16.f32 "
        "{%0,%1,%2,%3}, {%4,%5,%6,%7}, {%8,%9}, {%0,%1,%2,%3};"
        : "+f"(c[0]), "+f"(c[1]), "+f"(c[2]), "+f"(c[3])
        : "r"(a[0]), "r"(a[1]), "r"(a[2]), "r"(a[3]), "r"(b0), "r"(b1));
}
#define MBARRIER_INIT(m, c) \
    asm volatile("mbarrier.init.shared.b64 [%0], %1;" :: "r"(m), "r"(c) : "memory")
#define MBARRIER_EXPECT_TX(m, b) \
    asm volatile("mbarrier.arrive.expect_tx.shared.b64 _, [%0], %1;" :: "r"(m), "r"(b) : "memory")
#define MBARRIER_WAIT_PARITY(m, par) do {                                     \
    uint32_t _m = (m), _p = (par), _d;                                        \
    asm volatile("{\n\t.reg .pred p;\n\t"                                     \
        "mbarrier.try_wait.parity.acquire.cta.shared::cta.b64 p, [%1], %2;\n\t" \
        "selp.b32 %0, 1, 0, p;\n\t}" : "=r"(_d) : "r"(_m), "r"(_p) : "memory"); \
    if (!_d) {                                                                \
        asm volatile("{\n\t.reg .pred P1;\n\t"                                \
            "W0_%=:\n\t"                                                      \
            "mbarrier.try_wait.parity.acquire.cta.shared::cta.b64 P1, [%0], %1, 0x989680;\n\t" \
            "@P1 bra.uni W1_%=;\n\t"                                          \
            "bra.uni W0_%=;\n\t"                                              \
            "W1_%=:\n\t}" :: "r"(_m), "r"(_p) : "memory");                    \
    }                                                                         \
} while (0)
#define BULK_G2S(dst, src, bytes, mbar)                                       \
    asm volatile("cp.async.bulk.shared::cluster.global.mbarrier::complete_tx::bytes [%0], [%1], %2, [%3];" \
        :: "r"(dst), "l"(src), "r"(bytes), "r"(mbar) : "memory")
// order-preserving float<->uint
__device__ __forceinline__ uint32_t fenc(float f) {
    uint32_t b = __float_as_uint(f);
    return b ^ ((b & 0x80000000u) ? 0xFFFFFFFFu : 0x80000000u);
}
__device__ __forceinline__ float fdec(uint32_t u) {
    uint32_t b = u ^ ((u & 0x80000000u) ? 0x80000000u : 0xFFFFFFFFu);
    return __uint_as_float(b);
}

// ---------------------------------------------------------------- prep
__global__ void prep_e_kernel(const float* __restrict__ emb) {
    __shared__ float part[8];
    int k = blockIdx.x, d = threadIdx.x;
    float v = emb[(size_t)k * D_DIM + d];
    g_eb[(size_t)k * PITCH_H + d] = __bfloat16_as_ushort(__float2bfloat16(v));
    float s = v * v;
    #pragma unroll
    for (int o = 16; o > 0; o >>= 1) s += __shfl_xor_sync(0xffffffffu, s, o);
    if ((d & 31) == 0) part[d >> 5] = s;
    __syncthreads();
    if (d == 0) {
        float t = 0.f;
        #pragma unroll
        for (int i = 0; i < 8; ++i) t += part[i];
        g_e2[k] = t;
    }
}
// z NCHW [b][d][p] -> g_zt fp32 + g_zh bf16(padded pitch); zz partials
__global__ void prep_z_kernel(const float* __restrict__ z) {
    __shared__ float tile[32][33];
    int b = blockIdx.z, d0 = blockIdx.y * 32, p0 = blockIdx.x * 32;
    int tx = threadIdx.x, ty = threadIdx.y;          // (32,8)
    #pragma unroll
    for (int r = 0; r < 4; ++r)
        tile[ty + 8 * r][tx] = z[((size_t)b * D_DIM + d0 + ty + 8 * r) * P_PER_B + p0 + tx];
    __syncthreads();
    #pragma unroll
    for (int r = 0; r < 4; ++r) {
        int pl = ty + 8 * r;
        float v = tile[tx][pl];
        size_t p = (size_t)b * P_PER_B + p0 + pl;
        g_zt[p * D_DIM + d0 + tx] = v;
        g_zh[p * PITCH_H + d0 + tx] = __bfloat16_as_ushort(__float2bfloat16(v));
        float s = v * v;
        #pragma unroll
        for (int o2 = 16; o2 > 0; o2 >>= 1) s += __shfl_xor_sync(0xffffffffu, s, o2);
        if (tx == 0) g_zzp[d0 >> 5][p] = s;
    }
}

// ---------------------------------------------------------------- main
// grid 256, block 256 (8 warps): warp (w&3)=64-row M slab, (w>>2)=32-col N half.
__global__ void __launch_bounds__(NTHR, 1)
vq_hmma_kernel(const float* __restrict__ emb, float* __restrict__ out) {
    extern __shared__ __align__(16) char sm[];
    const uint32_t sb = smem_u32(sm);
    const int tid = threadIdx.x, w = tid >> 5, l = tid & 31;
    const int warp_m = w & 3, warp_n = w >> 2;
    const int m_base = blockIdx.x * MP;

    uint32_t* rowmin_u = reinterpret_cast<uint32_t*>(sm + OFF_ROWMIN);
    unsigned long long* slot = reinterpret_cast<unsigned long long*>(sm + OFF_SLOT);
    float* zzs  = reinterpret_cast<float*>(sm + OFF_ZZS);
    uint2* list = reinterpret_cast<uint2*>(sm + OFF_LIST);
    int*   cnt  = reinterpret_cast<int*>(sm + OFF_CNT);
    const uint32_t mbA = sb + OFF_MBAR, mb0 = sb + OFF_MBAR + 8, mb1 = sb + OFF_MBAR + 16;

    rowmin_u[tid] = 0xFFFFFFFFu;
    slot[tid] = ~0ull;
    {   // zz = fixed-order sum of partials (deterministic)
        float p0 = g_zzp[0][m_base + tid], p1 = g_zzp[1][m_base + tid];
        float p2 = g_zzp[2][m_base + tid], p3 = g_zzp[3][m_base + tid];
        float p4 = g_zzp[4][m_base + tid], p5 = g_zzp[5][m_base + tid];
        float p6 = g_zzp[6][m_base + tid], p7 = g_zzp[7][m_base + tid];
        zzs[tid] = ((p0 + p1) + (p2 + p3)) + ((p4 + p5) + (p6 + p7));
    }
    if (tid == 0) {
        *cnt = 0;
        MBARRIER_INIT(mbA, 1);
        MBARRIER_INIT(mb0, 1);
        MBARRIER_INIT(mb1, 1);
    }
    __syncthreads();     // mbarrier init + smem init visible

    // ---- bulk prefetch: A slab + B tiles 0,1 (one instruction each)
    if (tid == 0) {
        MBARRIER_EXPECT_TX(mbA, A_BYTES);
        BULK_G2S(sb + OFF_A, (const void*)(g_zh + (size_t)m_base * PITCH_H), A_BYTES, mbA);
        MBARRIER_EXPECT_TX(mb0, BT_BYTES);
        BULK_G2S(sb + OFF_B0, (const void*)g_eb, BT_BYTES, mb0);
        MBARRIER_EXPECT_TX(mb1, BT_BYTES);
        BULK_G2S(sb + OFF_B1, (const void*)((const char*)g_eb + BT_BYTES), BT_BYTES, mb1);
    }
    MBARRIER_WAIT_PARITY(mbA, 0);

    float rm[4][2];                       // running per-row min (registers)
    #pragma unroll
    for (int mt = 0; mt < 4; ++mt) { rm[mt][0] = 3.4e38f; rm[mt][1] = 3.4e38f; }

    for (int t = 0; t < TILES; ++t) {
        MBARRIER_WAIT_PARITY((t & 1) ? mb1 : mb0, (t >> 1) & 1);

        const uint32_t Bb = sb + ((t & 1) ? OFF_B1 : OFF_B0);

        float acc[4][4][4];
        #pragma unroll
        for (int mt = 0; mt < 4; ++mt)
            #pragma unroll
            for (int nt = 0; nt < 4; ++nt)
                #pragma unroll
                for (int c = 0; c < 4; ++c) acc[mt][nt][c] = 0.f;

        #pragma unroll
        for (int ks = 0; ks < 16; ++ks) {
            uint32_t a[4][4];
            #pragma unroll
            for (int mt = 0; mt < 4; ++mt) {
                uint32_t addr = sb + OFF_A
                              + (warp_m * 64 + mt * 16 + (l & 15)) * A_ROW
                              + (ks * 16 + ((l >> 4) & 1) * 8) * 2;
                ldmatrix_x4(a[mt][0], a[mt][1], a[mt][2], a[mt][3], addr);
            }
            uint32_t b[2][4];
            #pragma unroll
            for (int j = 0; j < 2; ++j) {
                uint32_t addr = Bb
                              + (warp_n * 32 + j * 16 + ((l >> 4) & 1) * 8 + (l & 7)) * PITCH_B
                              + (ks * 16 + ((l >> 3) & 1) * 8) * 2;
                ldmatrix_x4(b[j][0], b[j][1], b[j][2], b[j][3], addr);
            }
            #pragma unroll
            for (int mt = 0; mt < 4; ++mt)
                #pragma unroll
                for (int nt = 0; nt < 4; ++nt)
                    mma_bf16(acc[mt][nt], a[mt],
                             b[nt >> 1][(nt & 1) * 2], b[nt >> 1][(nt & 1) * 2 + 1]);
        }

        // ---- epilogue: scores -> register row-min -> leader atomics -> gate
        const int n0 = t * NTILE + warp_n * 32;
        float e2v[4][2];
        #pragma unroll
        for (int nt = 0; nt < 4; ++nt) {
            e2v[nt][0] = __ldg(&g_e2[n0 + nt * 8 + (l & 3) * 2]);
            e2v[nt][1] = __ldg(&g_e2[n0 + nt * 8 + (l & 3) * 2 + 1]);
        }
        float rmin[4][2];
        #pragma unroll
        for (int mt = 0; mt < 4; ++mt) { rmin[mt][0] = 3.4e38f; rmin[mt][1] = 3.4e38f; }
        #pragma unroll
        for (int mt = 0; mt < 4; ++mt)
            #pragma unroll
            for (int nt = 0; nt < 4; ++nt)
                #pragma unroll
                for (int c = 0; c < 4; ++c) {
                    float s = __fmaf_rn(-2.f, acc[mt][nt][c], e2v[nt][c & 1]);
                    acc[mt][nt][c] = s;                       // acc now holds scores
                    rmin[mt][c >> 1] = fminf(rmin[mt][c >> 1], s);
                }
        #pragma unroll
        for (int mt = 0; mt < 4; ++mt)
            #pragma unroll
            for (int h = 0; h < 2; ++h) {
                float v = rmin[mt][h];                        // quad shares rows
                v = fminf(v, __shfl_xor_sync(0xffffffffu, v, 1));
                v = fminf(v, __shfl_xor_sync(0xffffffffu, v, 2));
                rmin[mt][h] = v;
            }
        if ((l & 3) == 0) {
            #pragma unroll
            for (int mt = 0; mt < 4; ++mt)
                #pragma unroll
                for (int h = 0; h < 2; ++h)
                    atomicMin(&rowmin_u[warp_m * 64 + mt * 16 + (l >> 2) + h * 8],
                              fenc(rmin[mt][h]));
        }
        #pragma unroll
        for (int mt = 0; mt < 4; ++mt)
            #pragma unroll
            for (int h = 0; h < 2; ++h) {
                // own fresh min + possibly-stale shared (stale only admits extras)
                float sh = fdec(rowmin_u[warp_m * 64 + mt * 16 + (l >> 2) + h * 8]);
                rm[mt][h] = fminf(fminf(rm[mt][h], rmin[mt][h]), sh);
            }
        #pragma unroll
        for (int mt = 0; mt < 4; ++mt)
            #pragma unroll
            for (int nt = 0; nt < 4; ++nt)
                #pragma unroll
                for (int c = 0; c < 4; ++c) {
                    float s = acc[mt][nt][c];
                    if (s <= rm[mt][c >> 1] + TAU) {
                        int row  = warp_m * 64 + mt * 16 + (l >> 2) + (c >> 1) * 8;
                        int code = n0 + nt * 8 + (l & 3) * 2 + (c & 1);
                        int pos = atomicAdd(cnt, 1);
                        if (pos < CAP)
                            list[pos] = make_uint2((uint32_t)(row << 10) | code,
                                                   __float_as_uint(s));
                    }
                }
        __syncthreads();   // all reads of buffer t&1 retired; rowmin published

        if (t + 2 < TILES && tid == 0) {   // refill buffer t&1 with tile t+2
            uint32_t mb = (t & 1) ? mb1 : mb0;
            uint32_t dst = sb + ((t & 1) ? OFF_B1 : OFF_B0);
            MBARRIER_EXPECT_TX(mb, BT_BYTES);
            BULK_G2S(dst, (const void*)((const char*)g_eb + (size_t)(t + 2) * BT_BYTES),
                     BT_BYTES, mb);
        }
    }

    int total = *cnt;
    if (total <= CAP) {
        // ---- exact fp32 refine of surviving candidates
        for (int i = tid; i < total; i += NTHR) {
            uint2 ent = list[i];
            int row = ent.x >> 10, code = ent.x & 1023;
            if (__uint_as_float(ent.y) > fdec(rowmin_u[row]) + TAU) continue;
            const float* zr = g_zt + (size_t)(m_base + row) * D_DIM;
            const float* er = emb + (size_t)code * D_DIM;
            float a0 = 0.f, a1 = 0.f, a2 = 0.f, a3 = 0.f;
            #pragma unroll 4
            for (int d = 0; d < D_DIM; d += 16) {
                float4 z0 = *reinterpret_cast<const float4*>(zr + d);
                float4 e0 = *reinterpret_cast<const float4*>(er + d);
                float4 z1 = *reinterpret_cast<const float4*>(zr + d + 4);
                float4 e1 = *reinterpret_cast<const float4*>(er + d + 4);
                float4 z2 = *reinterpret_cast<const float4*>(zr + d + 8);
                float4 e2_ = *reinterpret_cast<const float4*>(er + d + 8);
                float4 z3 = *reinterpret_cast<const float4*>(zr + d + 12);
                float4 e3 = *reinterpret_cast<const float4*>(er + d + 12);
                a0 = __fmaf_rn(z0.x, e0.x, a0); a0 = __fmaf_rn(z0.y, e0.y, a0);
                a0 = __fmaf_rn(z0.z, e0.z, a0); a0 = __fmaf_rn(z0.w, e0.w, a0);
                a1 = __fmaf_rn(z1.x, e1.x, a1); a1 = __fmaf_rn(z1.y, e1.y, a1);
                a1 = __fmaf_rn(z1.z, e1.z, a1); a1 = __fmaf_rn(z1.w, e1.w, a1);
                a2 = __fmaf_rn(z2.x, e2_.x, a2); a2 = __fmaf_rn(z2.y, e2_.y, a2);
                a2 = __fmaf_rn(z2.z, e2_.z, a2); a2 = __fmaf_rn(z2.w, e2_.w, a2);
                a3 = __fmaf_rn(z3.x, e3.x, a3); a3 = __fmaf_rn(z3.y, e3.y, a3);
                a3 = __fmaf_rn(z3.z, e3.z, a3); a3 = __fmaf_rn(z3.w, e3.w, a3);
            }
            float dot = (a0 + a1) + (a2 + a3);
            float q = __fadd_rn(__fmaf_rn(-2.f, dot, zzs[row]), g_e2[code]);
            unsigned long long key =
                ((unsigned long long)__float_as_uint(q) << 32) | (uint32_t)code;
            atomicMin(&slot[row], key);
        }
    } else {
        // overflow fallback (prob ~0): brute-force own point exactly
        const float* zr = g_zt + (size_t)(m_base + tid) * D_DIM;
        float zzv = zzs[tid];
        unsigned long long best = ~0ull;
        for (int code = 0; code < K_CODES; ++code) {
            const float* er = emb + (size_t)code * D_DIM;
            float acc = 0.f;
            #pragma unroll 8
            for (int d = 0; d < D_DIM; ++d) acc = __fmaf_rn(zr[d], er[d], acc);
            float q = __fadd_rn(__fmaf_rn(-2.f, acc, zzv), g_e2[code]);
            unsigned long long key =
                ((unsigned long long)__float_as_uint(q) << 32) | (uint32_t)code;
            if (key < best) best = key;
        }
        slot[tid] = best;
    }
    __syncthreads();

    out[m_base + tid] = (float)(uint32_t)(slot[tid] & 0xffffffffull);
}

// ---------------------------------------------------------------- launch
extern "C" void kernel_launch(void* const* d_in, const int* in_sizes, int n_in,
                              void* d_out, int out_size) {
    const float* z   = (const float*)d_in[0];
    const float* emb = (const float*)d_in[1];
    if (n_in >= 2 && in_sizes[0] == K_CODES * D_DIM) {
        emb = (const float*)d_in[0];
        z   = (const float*)d_in[1];
    }
    float* out = (float*)d_out;

    static int smem_set = 0;
    if (!smem_set) {
        cudaFuncSetAttribute(vq_hmma_kernel,
                             cudaFuncAttributeMaxDynamicSharedMemorySize, SMEM_TOTAL);
        smem_set = 1;
    }

    prep_e_kernel<<<K_CODES, 256>>>(emb);
    prep_z_kernel<<<dim3(32, 8, N_BATCH), dim3(32, 8)>>>(z);
    vq_hmma_kernel<<<N_PTS / MP, NTHR, SMEM_TOTAL>>>(emb, out);
}